// round 1
// baseline (speedup 1.0000x reference)
#include <cuda_runtime.h>
#include <math.h>

#define EPS 1e-5f
#define CC 64
#define NN 8
#define HW 65536
#define P1 128
#define NB1 (HW/P1)      /* 512 */
#define CH25 1024
#define NB25 (HW/CH25)   /* 64 */
#define P3 256
#define NB3 (HW/P3)      /* 256 */
#define WST 68           /* padded row stride for weight tile */

// ---------------- scratch (__device__ globals; no allocation) ----------------
__device__ float g_val[(size_t)2*NN*HW*CC];   // 256 MiB, layout [side][n][pix][c]
__device__ float g_k[2*NN*HW];                // silu'd key values
__device__ float g_psum[2*NN*NB1*CC];
__device__ float g_pmax[2*NN*NB1*CC];
__device__ float g_pkm[2*NN*NB1];
__device__ float g_pkz[2*NN*NB1];
__device__ float g_avg[2*NN*CC];
__device__ float g_mx[2*NN*CC];
__device__ float g_kM[2*NN];
__device__ float g_kZ[2*NN];
__device__ float g_feap[2*NN*NB25*CC];
__device__ float g_gate[2*NN*CC];

__device__ __forceinline__ float sigmoidf_(float x){ return 1.f/(1.f+expf(-x)); }
__device__ __forceinline__ float siluf_(float x){ return x/(1.f+expf(-x)); }

// ---------------- kernel 1: convs + per-block stats + val/key store ----------------
extern __shared__ float sm1[];

__global__ __launch_bounds__(256) void k1(
    const float* __restrict__ rgb, const float* __restrict__ ir,
    const float* __restrict__ conv_w, const float* __restrict__ val_w,
    const float* __restrict__ key_w,
    const float* __restrict__ key_g, const float* __restrict__ key_b,
    const float* __restrict__ key_m, const float* __restrict__ key_v,
    const float* __restrict__ val_g, const float* __restrict__ val_b,
    const float* __restrict__ val_m, const float* __restrict__ val_v)
{
    float* xs  = sm1;              // [64][128]
    float* wsT = sm1 + 8192;       // [64][WST]
    float* kws = sm1 + 12544;      // [64]
    float* vsc = sm1 + 12608;      // [64]
    float* vsh = sm1 + 12672;      // [64]
    float* kk  = sm1 + 12736;      // [128]

    const int tid = threadIdx.x;
    const int s = blockIdx.z, n = blockIdx.y, blk = blockIdx.x;
    const int e0 = blk * P1;
    const float* x = (s == 0 ? rgb : ir) + (size_t)n * CC * HW;

    // load x tile [64 ch][128 pix] (float4, coalesced)
    #pragma unroll
    for (int i = 0; i < 8; i++) {
        int idx = tid + i * 256;          // 2048 float4 total
        int c = idx >> 5, p4 = idx & 31;
        float4 v = *reinterpret_cast<const float4*>(x + (size_t)c * HW + e0 + (p4 << 2));
        *reinterpret_cast<float4*>(xs + c * P1 + (p4 << 2)) = v;
    }
    // conv_w transposed into smem: wsT[c][o]
    for (int idx = tid; idx < 4096; idx += 256) {
        int o = idx >> 6, c = idx & 63;
        wsT[c * WST + o] = conv_w[idx];
    }
    if (tid < 64) kws[tid] = key_w[tid];
    __syncthreads();

    const int og = tid >> 5, pg = tid & 31;   // warp = 8 out-channels, lane = 4 pixels

    // ---- phase A: xc conv, reduce sum/max over pixels ----
    float a0[8], a1[8], a2[8], a3[8];
    #pragma unroll
    for (int j = 0; j < 8; j++) { a0[j]=0.f; a1[j]=0.f; a2[j]=0.f; a3[j]=0.f; }
    #pragma unroll 8
    for (int c = 0; c < CC; c++) {
        float4 xv = *reinterpret_cast<const float4*>(xs + c * P1 + (pg << 2));
        const float* wr = wsT + c * WST + (og << 3);
        #pragma unroll
        for (int j = 0; j < 8; j++) {
            float w = wr[j];
            a0[j] = fmaf(xv.x, w, a0[j]);
            a1[j] = fmaf(xv.y, w, a1[j]);
            a2[j] = fmaf(xv.z, w, a2[j]);
            a3[j] = fmaf(xv.w, w, a3[j]);
        }
    }
    #pragma unroll
    for (int j = 0; j < 8; j++) {
        float sv = a0[j] + a1[j] + a2[j] + a3[j];
        float mv = fmaxf(fmaxf(a0[j], a1[j]), fmaxf(a2[j], a3[j]));
        #pragma unroll
        for (int off = 16; off; off >>= 1) {
            sv += __shfl_down_sync(0xffffffffu, sv, off);
            mv = fmaxf(mv, __shfl_down_sync(0xffffffffu, mv, off));
        }
        if (pg == 0) {
            size_t b = ((size_t)(s * NN + n) * NB1 + blk) * CC + (og << 3) + j;
            g_psum[b] = sv; g_pmax[b] = mv;
        }
    }

    // ---- key conv (1 x C) for 128 pixels ----
    if (tid < P1) {
        float ka = 0.f;
        #pragma unroll 8
        for (int c = 0; c < CC; c++) ka = fmaf(kws[c], xs[c * P1 + tid], ka);
        float ks = key_g[0] * rsqrtf(key_v[0] + EPS);
        float kb = key_b[0] - key_m[0] * ks;
        float t = ka * ks + kb;
        float kv = siluf_(t);
        kk[tid] = kv;
        g_k[(size_t)(s * NN + n) * HW + e0 + tid] = kv;
    }
    __syncthreads();

    if (tid < 32) {
        float m = fmaxf(fmaxf(kk[tid], kk[tid + 32]), fmaxf(kk[tid + 64], kk[tid + 96]));
        #pragma unroll
        for (int off = 16; off; off >>= 1) m = fmaxf(m, __shfl_xor_sync(0xffffffffu, m, off));
        float z = expf(kk[tid] - m) + expf(kk[tid + 32] - m) +
                  expf(kk[tid + 64] - m) + expf(kk[tid + 96] - m);
        #pragma unroll
        for (int off = 16; off; off >>= 1) z += __shfl_xor_sync(0xffffffffu, z, off);
        if (tid == 0) { int b = (s * NN + n) * NB1 + blk; g_pkm[b] = m; g_pkz[b] = z; }
    }

    // ---- phase B: val conv (reload weights) ----
    for (int idx = tid; idx < 4096; idx += 256) {
        int o = idx >> 6, c = idx & 63;
        wsT[c * WST + o] = val_w[idx];
    }
    if (tid < 64) {
        float sc = val_g[tid] * rsqrtf(val_v[tid] + EPS);
        vsc[tid] = sc; vsh[tid] = val_b[tid] - val_m[tid] * sc;
    }
    __syncthreads();

    #pragma unroll
    for (int j = 0; j < 8; j++) { a0[j]=0.f; a1[j]=0.f; a2[j]=0.f; a3[j]=0.f; }
    #pragma unroll 8
    for (int c = 0; c < CC; c++) {
        float4 xv = *reinterpret_cast<const float4*>(xs + c * P1 + (pg << 2));
        const float* wr = wsT + c * WST + (og << 3);
        #pragma unroll
        for (int j = 0; j < 8; j++) {
            float w = wr[j];
            a0[j] = fmaf(xv.x, w, a0[j]);
            a1[j] = fmaf(xv.y, w, a1[j]);
            a2[j] = fmaf(xv.z, w, a2[j]);
            a3[j] = fmaf(xv.w, w, a3[j]);
        }
    }
    float* vout = g_val + ((size_t)(s * NN + n) * HW + e0) * CC;
    float vv[8];
    #pragma unroll
    for (int p = 0; p < 4; p++) {
        float* ap = (p == 0 ? a0 : (p == 1 ? a1 : (p == 2 ? a2 : a3)));
        #pragma unroll
        for (int j = 0; j < 8; j++) {
            int o = (og << 3) + j;
            float t = fmaf(ap[j], vsc[o], vsh[o]);
            vv[j] = siluf_(t);
        }
        size_t base = (size_t)((pg << 2) + p) * CC + (og << 3);
        *reinterpret_cast<float4*>(vout + base)     = make_float4(vv[0], vv[1], vv[2], vv[3]);
        *reinterpret_cast<float4*>(vout + base + 4) = make_float4(vv[4], vv[5], vv[6], vv[7]);
    }
}

// ---------------- block-of-64 reductions ----------------
__device__ __forceinline__ float blk64_max(float v, float* red, int c) {
    red[c] = v; __syncthreads();
    for (int st = 32; st >= 1; st >>= 1) { if (c < st) red[c] = fmaxf(red[c], red[c + st]); __syncthreads(); }
    float r = red[0]; __syncthreads(); return r;
}
__device__ __forceinline__ float blk64_sum(float v, float* red, int c) {
    red[c] = v; __syncthreads();
    for (int st = 32; st >= 1; st >>= 1) { if (c < st) red[c] += red[c + st]; __syncthreads(); }
    float r = red[0]; __syncthreads(); return r;
}

// ---------------- kernel 2: finalize stats (avg/mx softmax, key M/Z) ----------------
__global__ __launch_bounds__(64) void k2(const float* __restrict__ conv_b)
{
    const int n = blockIdx.x, s = blockIdx.y, c = threadIdx.x;
    __shared__ float red[64];
    const size_t base = (size_t)(s * NN + n) * NB1;

    float sv = 0.f, mv = -3.0e38f;
    for (int b = 0; b < NB1; b++) {
        sv += g_psum[(base + b) * CC + c];
        mv = fmaxf(mv, g_pmax[(base + b) * CC + c]);
    }
    float mean = sv * (1.f / HW) + conv_b[c];
    float mx   = mv + conv_b[c];

    float am = blk64_max(mean, red, c);
    float ea = expf(mean - am);
    float za = blk64_sum(ea, red, c);
    g_avg[(s * NN + n) * CC + c] = ea / za;

    float mm = blk64_max(mx, red, c);
    float em = expf(mx - mm);
    float zm = blk64_sum(em, red, c);
    g_mx[(s * NN + n) * CC + c] = em / zm;

    float km = -3.0e38f;
    for (int b = c; b < NB1; b += 64) km = fmaxf(km, g_pkm[base + b]);
    float M = blk64_max(km, red, c);
    float z = 0.f;
    for (int b = c; b < NB1; b += 64) z += g_pkz[base + b] * expf(g_pkm[base + b] - M);
    float Z = blk64_sum(z, red, c);
    if (c == 0) { g_kM[s * NN + n] = M; g_kZ[s * NN + n] = Z; }
}

// ---------------- kernel 2.5: fea partials = sum_e val[1-s]*softkey[s] ----------------
__global__ __launch_bounds__(256) void k25()
{
    const int s = blockIdx.z, n = blockIdx.y, ch = blockIdx.x;
    const int tid = threadIdx.x;
    const int e0 = ch * CH25;
    __shared__ float wk[CH25];
    __shared__ float pr[256];

    const float M = g_kM[s * NN + n];
    const float invZ = 1.f / g_kZ[s * NN + n];
    const float* kp = g_k + (size_t)(s * NN + n) * HW + e0;
    for (int i = tid; i < CH25; i += 256) wk[i] = expf(kp[i] - M) * invZ;
    __syncthreads();

    const int c = tid & 63, r = tid >> 6;
    const float* vp = g_val + ((size_t)((1 - s) * NN + n) * HW + e0) * CC;
    float acc = 0.f;
    for (int i = r; i < CH25; i += 4) acc = fmaf(vp[(size_t)i * CC + c], wk[i], acc);
    pr[tid] = acc; __syncthreads();
    if (r == 0)
        g_feap[((size_t)(s * NN + n) * NB25 + ch) * CC + c] =
            pr[c] + pr[64 + c] + pr[128 + c] + pr[192 + c];
}

// ---------------- kernel 2.75: gate = sigmoid(LN(fea @ convb^T)) ----------------
__global__ __launch_bounds__(64) void k27(
    const float* __restrict__ convb_w, const float* __restrict__ ln_g, const float* __restrict__ ln_b)
{
    const int n = blockIdx.x, s = blockIdx.y, c = threadIdx.x;
    __shared__ float feas[64];
    __shared__ float red[64];
    const size_t base = (size_t)(s * NN + n) * NB25 * CC;
    float f = 0.f;
    for (int b = 0; b < NB25; b++) f += g_feap[base + (size_t)b * CC + c];
    feas[c] = f; __syncthreads();

    float g = 0.f;
    #pragma unroll 8
    for (int j = 0; j < CC; j++) g = fmaf(convb_w[c * CC + j], feas[j], g);

    float mu  = blk64_sum(g, red, c) * (1.f / CC);
    float d   = g - mu;
    float var = blk64_sum(d * d, red, c) * (1.f / CC);
    float zz  = d * rsqrtf(var + EPS) * ln_g[c] + ln_b[c];
    g_gate[(s * NN + n) * CC + c] = sigmoidf_(zz);
}

// ---------------- kernel 3: output = gate * half + me ----------------
__global__ __launch_bounds__(256) void k3(
    const float* __restrict__ rgb, const float* __restrict__ ir, float* __restrict__ out,
    const float* __restrict__ half_w,
    const float* __restrict__ half_g, const float* __restrict__ half_b,
    const float* __restrict__ half_m, const float* __restrict__ half_v)
{
    const int s = blockIdx.z, n = blockIdx.y;
    const int e0 = blockIdx.x * P3;
    const int tid = threadIdx.x;
    __shared__ __align__(16) float avs[64];
    __shared__ __align__(16) float mxs[64];
    __shared__ __align__(16) float gts[64];
    if (tid < 64) {
        int i = (s * NN + n) * CC + tid;
        avs[tid] = g_avg[i]; mxs[tid] = g_mx[i]; gts[tid] = g_gate[i];
    }
    __syncthreads();

    const float* vp = g_val + ((size_t)((1 - s) * NN + n) * HW + e0 + tid) * CC;
    float aA = 0.f, aM = 0.f;
    #pragma unroll
    for (int c4 = 0; c4 < 16; c4++) {
        float4 v = reinterpret_cast<const float4*>(vp)[c4];
        float4 a = reinterpret_cast<const float4*>(avs)[c4];
        float4 m = reinterpret_cast<const float4*>(mxs)[c4];
        aA += v.x * a.x + v.y * a.y + v.z * a.z + v.w * a.w;
        aM += v.x * m.x + v.y * m.y + v.z * m.z + v.w * m.w;
    }
    float hs = half_g[0] * rsqrtf(half_v[0] + EPS);
    float hb = half_b[0] - half_m[0] * hs;
    float pre = half_w[0] * aA + half_w[1] * aM;
    float hlf = siluf_(pre * hs + hb);

    const float* xme = (s == 0 ? rgb : ir) + (size_t)n * CC * HW;
    float* op = out + (size_t)(s * NN + n) * CC * HW;
    #pragma unroll 4
    for (int c = 0; c < CC; c++) {
        size_t idx = (size_t)c * HW + e0 + tid;
        op[idx] = fmaf(gts[c], hlf, xme[idx]);
    }
}

// ---------------- launch ----------------
extern "C" void kernel_launch(void* const* d_in, const int* in_sizes, int n_in,
                              void* d_out, int out_size)
{
    const float* rgb     = (const float*)d_in[0];
    const float* ir      = (const float*)d_in[1];
    const float* conv_w  = (const float*)d_in[2];
    const float* conv_b  = (const float*)d_in[3];
    const float* key_w   = (const float*)d_in[4];
    const float* key_g   = (const float*)d_in[5];
    const float* key_b   = (const float*)d_in[6];
    const float* key_m   = (const float*)d_in[7];
    const float* key_v   = (const float*)d_in[8];
    const float* val_w   = (const float*)d_in[9];
    const float* val_g   = (const float*)d_in[10];
    const float* val_b   = (const float*)d_in[11];
    const float* val_m   = (const float*)d_in[12];
    const float* val_v   = (const float*)d_in[13];
    const float* convb_w = (const float*)d_in[14];
    const float* half_w  = (const float*)d_in[15];
    const float* half_g  = (const float*)d_in[16];
    const float* half_b  = (const float*)d_in[17];
    const float* half_m  = (const float*)d_in[18];
    const float* half_v  = (const float*)d_in[19];
    const float* ln_g    = (const float*)d_in[20];
    const float* ln_b    = (const float*)d_in[21];
    float* out = (float*)d_out;

    const size_t smem1 = 12864 * sizeof(float);   // 51456 B
    cudaFuncSetAttribute(k1, cudaFuncAttributeMaxDynamicSharedMemorySize, (int)smem1);

    k1<<<dim3(NB1, NN, 2), 256, smem1>>>(rgb, ir, conv_w, val_w, key_w,
                                         key_g, key_b, key_m, key_v,
                                         val_g, val_b, val_m, val_v);
    k2<<<dim3(NN, 2), 64>>>(conv_b);
    k25<<<dim3(NB25, NN, 2), 256>>>();
    k27<<<dim3(NN, 2), 64>>>(convb_w, ln_g, ln_b);
    k3<<<dim3(NB3, NN, 2), 256>>>(rgb, ir, out, half_w, half_g, half_b, half_m, half_v);
}